// round 6
// baseline (speedup 1.0000x reference)
#include <cuda_runtime.h>

// Segment mean pooling via fixed-stride bucket sort + gather-reduce.
//   1. scatter: perm[seg*128 + atomicAdd(cursor[seg])] = row (2 rows/thread,
//      ids dtype detected inline from the first 16 bytes)
//   2. gather: 1 warp/segment, half-warp float4 scheme (2 rows per step,
//      512B per load instruction), shfl_xor(16) combine, 1/cnt multiply.
//      Gather RESETS cursor[seg]=0 after use -> no init kernel needed
//      (device globals are zero-initialized at module load; the reset
//      restores the invariant for every graph replay).

#define D_DIM 64
#define SEG_CAP 131072
#define BUCKET 128          // max rows per segment (Poisson(40): 14-sigma safe)
#define PERM_WORDS (SEG_CAP * BUCKET)

__device__ int g_cursor[SEG_CAP];    // zero at module load; gather re-zeroes
__device__ int g_perm[PERM_WORDS];   // 64 MB static scratch

// ---- 1. scatter row indices into fixed-stride buckets (2 rows/thread) ----
// dtype detection: under the int64 interpretation every valid id is in
// [0, S). If ids are really int32, an int64 read pairs two ids
// (lo + hi*2^32) and goes out of range unless hi == 0 (P ~ 1e-5 per slot;
// two slots -> P(misdetect) ~ 1e-10).
__global__ void scatter_kernel(const void* __restrict__ ids, int n_rows, int S) {
    int i = blockIdx.x * blockDim.x + threadIdx.x;   // pair index
    int r0 = i * 2;
    if (r0 >= n_rows) return;

    // Inline dtype check (one 16B broadcast load, L1-resident)
    longlong2 probe = __ldg((const longlong2*)ids);
    bool is_i32 = (probe.x < 0) | (probe.x >= (long long)S) |
                  (probe.y < 0) | (probe.y >= (long long)S);

    int seg0, seg1;
    if (is_i32) {
        int2 v = __ldg(((const int2*)ids) + i);
        seg0 = v.x; seg1 = v.y;
    } else {
        longlong2 v = __ldg(((const longlong2*)ids) + i);
        seg0 = (int)v.x; seg1 = (int)v.y;
    }

    int pos0 = atomicAdd(&g_cursor[seg0], 1);
    if (pos0 < BUCKET) g_perm[(seg0 << 7) + pos0] = r0;

    if (r0 + 1 < n_rows) {
        int pos1 = atomicAdd(&g_cursor[seg1], 1);
        if (pos1 < BUCKET) g_perm[(seg1 << 7) + pos1] = r0 + 1;
    }
}

// ---- 2. gather-reduce: one warp per segment, half-warp float4 scheme ----
// Lanes 0-15 process even-step rows, lanes 16-31 odd-step rows. Each lane
// loads one float4 (16B): 32 lanes x 16B = 512B = 2 rows per instruction.
// Accumulators combined across halves with shfl_xor(16) at the end; lanes
// 0-15 store the 256B output row.
__global__ void gather_kernel(const float4* __restrict__ data4,
                              float4* __restrict__ out4, int S) {
    int gtid = blockIdx.x * blockDim.x + threadIdx.x;
    int warp = gtid >> 5;
    int lane = threadIdx.x & 31;
    if (warp >= S) return;

    int half = lane >> 4;    // 0 or 1
    int c    = lane & 15;    // float4 column within the row

    int cnt = g_cursor[warp];
    if (lane == 0) g_cursor[warp] = 0;   // reset for next graph replay
    if (cnt > BUCKET) cnt = BUCKET;
    int s128 = warp << 7;

    // Preload perm batches: lane k of batch b holds row index b*32+k.
    int p[4];
    #pragma unroll
    for (int b = 0; b < 4; b++) {
        p[b] = (b * 32 < cnt) ? __ldg(&g_perm[s128 + b * 32 + lane]) : 0;
    }

    float ax = 0.f, ay = 0.f, az = 0.f, aw = 0.f;

    #pragma unroll
    for (int b = 0; b < 4; b++) {
        int base = b * 32;
        if (base >= cnt) break;
        int nb = cnt - base;
        if (nb > 32) nb = 32;
        int myrow = p[b];

        int k = 0;
        // 8 rows (4 pairs) per iteration: 4 independent float4 loads/lane.
        #pragma unroll 4
        for (; k + 8 <= nb; k += 8) {
            int rA0 = __shfl_sync(0xffffffffu, myrow, k + 0 + half);
            int rA1 = __shfl_sync(0xffffffffu, myrow, k + 2 + half);
            int rA2 = __shfl_sync(0xffffffffu, myrow, k + 4 + half);
            int rA3 = __shfl_sync(0xffffffffu, myrow, k + 6 + half);
            float4 v0 = __ldg(&data4[(long long)rA0 * 16 + c]);
            float4 v1 = __ldg(&data4[(long long)rA1 * 16 + c]);
            float4 v2 = __ldg(&data4[(long long)rA2 * 16 + c]);
            float4 v3 = __ldg(&data4[(long long)rA3 * 16 + c]);
            ax += (v0.x + v1.x) + (v2.x + v3.x);
            ay += (v0.y + v1.y) + (v2.y + v3.y);
            az += (v0.z + v1.z) + (v2.z + v3.z);
            aw += (v0.w + v1.w) + (v2.w + v3.w);
        }
        // Pair tail (2 rows at a time)
        for (; k + 2 <= nb; k += 2) {
            int r = __shfl_sync(0xffffffffu, myrow, k + half);
            float4 v = __ldg(&data4[(long long)r * 16 + c]);
            ax += v.x; ay += v.y; az += v.z; aw += v.w;
        }
        // Odd row: half 0 only
        if (k < nb) {
            int r = __shfl_sync(0xffffffffu, myrow, k);
            if (half == 0) {
                float4 v = __ldg(&data4[(long long)r * 16 + c]);
                ax += v.x; ay += v.y; az += v.z; aw += v.w;
            }
        }
    }

    // Combine the two halves (lane i += lane i^16).
    ax += __shfl_xor_sync(0xffffffffu, ax, 16);
    ay += __shfl_xor_sync(0xffffffffu, ay, 16);
    az += __shfl_xor_sync(0xffffffffu, az, 16);
    aw += __shfl_xor_sync(0xffffffffu, aw, 16);

    if (half == 0) {
        float inv = (cnt > 0) ? (1.0f / (float)cnt) : 0.0f;
        float4 o;
        o.x = ax * inv; o.y = ay * inv; o.z = az * inv; o.w = aw * inv;
        out4[(long long)warp * 16 + c] = o;
    }
}

extern "C" void kernel_launch(void* const* d_in, const int* in_sizes, int n_in,
                              void* d_out, int out_size) {
    // Identify inputs by element count: data = largest (N*D), ids = N elems.
    int data_idx = 0;
    long long best = -1;
    for (int i = 0; i < n_in; i++) {
        if ((long long)in_sizes[i] > best) { best = in_sizes[i]; data_idx = i; }
    }
    long long n_rows_ll = best / D_DIM;

    int ids_idx = -1;
    for (int i = 0; i < n_in; i++) {
        if (i != data_idx && (long long)in_sizes[i] == n_rows_ll) { ids_idx = i; break; }
    }
    if (ids_idx < 0) {
        for (int i = 0; i < n_in; i++) {
            if (i != data_idx && in_sizes[i] > 1) { ids_idx = i; break; }
        }
    }

    const float* data = (const float*)d_in[data_idx];
    const void*  ids  = d_in[ids_idx];

    int n_rows = (int)n_rows_ll;
    int S = out_size / D_DIM;   // 100,000 segments
    if (S > SEG_CAP) S = SEG_CAP;

    const int TPB = 256;

    // 1. scatter row indices into buckets (2 rows per thread)
    int n_pairs = (n_rows + 1) / 2;
    scatter_kernel<<<(n_pairs + TPB - 1) / TPB, TPB>>>(ids, n_rows, S);

    // 2. gather-reduce (1 warp per segment; also resets cursors)
    long long g_threads = (long long)S * 32;
    gather_kernel<<<(int)((g_threads + TPB - 1) / TPB), TPB>>>(
        (const float4*)data, (float4*)d_out, S);
}

// round 7
// speedup vs baseline: 1.0326x; 1.0326x over previous
#include <cuda_runtime.h>

// Segment mean pooling via fixed-stride bucket sort + gather-reduce.
//   1. scatter: perm[seg*128 + atomicAdd(cursor[seg])] = row (4 rows/thread
//      to keep 4 atomic->store chains in flight; ids dtype detected inline)
//   2. gather: 1 warp/segment, half-warp float4 scheme, __ldcs streaming
//      data loads (protects L2-resident perm/cursor), higher occupancy via
//      __launch_bounds__ to deepen the DRAM request queue.
//      Gather RESETS cursor[seg]=0 after use -> no init kernel needed.

#define D_DIM 64
#define SEG_CAP 131072
#define BUCKET 128          // max rows per segment (Poisson(40): 14-sigma safe)
#define PERM_WORDS (SEG_CAP * BUCKET)

__device__ int g_cursor[SEG_CAP];    // zero at module load; gather re-zeroes
__device__ int g_perm[PERM_WORDS];   // 64 MB static scratch

// ---- 1. scatter row indices into fixed-stride buckets (4 rows/thread) ----
// dtype detection: under the int64 interpretation every valid id is in
// [0, S). If ids are really int32, an int64 read pairs two ids
// (lo + hi*2^32) -> out of range unless hi == 0 (P(misdetect) ~ 1e-10).
__global__ void scatter_kernel(const void* __restrict__ ids, int n_rows, int S) {
    int i = blockIdx.x * blockDim.x + threadIdx.x;   // quad index
    int r0 = i * 4;
    if (r0 >= n_rows) return;

    // Inline dtype check (one 16B broadcast load, L1-resident)
    longlong2 probe = __ldg((const longlong2*)ids);
    bool is_i32 = (probe.x < 0) | (probe.x >= (long long)S) |
                  (probe.y < 0) | (probe.y >= (long long)S);

    int seg[4];
    if (is_i32) {
        int4 v = __ldg(((const int4*)ids) + i);
        seg[0] = v.x; seg[1] = v.y; seg[2] = v.z; seg[3] = v.w;
    } else {
        longlong2 v0 = __ldg(((const longlong2*)ids) + 2 * i);
        longlong2 v1 = __ldg(((const longlong2*)ids) + 2 * i + 1);
        seg[0] = (int)v0.x; seg[1] = (int)v0.y;
        seg[2] = (int)v1.x; seg[3] = (int)v1.y;
    }

    // Issue all atomics first (independent), then the dependent stores:
    // 4 ATOMG round-trips overlap instead of serializing.
    int pos[4];
    int nv = n_rows - r0;
    #pragma unroll
    for (int j = 0; j < 4; j++) {
        if (j < nv) pos[j] = atomicAdd(&g_cursor[seg[j]], 1);
    }
    #pragma unroll
    for (int j = 0; j < 4; j++) {
        if (j < nv && pos[j] < BUCKET) g_perm[(seg[j] << 7) + pos[j]] = r0 + j;
    }
}

// ---- 2. gather-reduce: one warp per segment, half-warp float4 scheme ----
// Lanes 0-15 process even-step rows, lanes 16-31 odd-step rows; each lane
// loads one float4 -> 512B (2 rows) per load instruction across the warp.
// __ldcs on data: zero-reuse stream, evict-first keeps perm/cursor in L2.
__global__ void __launch_bounds__(256, 6)
gather_kernel(const float4* __restrict__ data4,
              float4* __restrict__ out4, int S) {
    int gtid = blockIdx.x * blockDim.x + threadIdx.x;
    int warp = gtid >> 5;
    int lane = threadIdx.x & 31;
    if (warp >= S) return;

    int half = lane >> 4;    // 0 or 1
    int c    = lane & 15;    // float4 column within the row

    int cnt = g_cursor[warp];
    if (lane == 0) g_cursor[warp] = 0;   // reset for next graph replay
    if (cnt > BUCKET) cnt = BUCKET;
    int s128 = warp << 7;

    // Preload perm batches: lane k of batch b holds row index b*32+k.
    int p[4];
    #pragma unroll
    for (int b = 0; b < 4; b++) {
        p[b] = (b * 32 < cnt) ? __ldg(&g_perm[s128 + b * 32 + lane]) : 0;
    }

    float ax = 0.f, ay = 0.f, az = 0.f, aw = 0.f;

    #pragma unroll
    for (int b = 0; b < 4; b++) {
        int base = b * 32;
        if (base >= cnt) break;
        int nb = cnt - base;
        if (nb > 32) nb = 32;
        int myrow = p[b];

        int k = 0;
        // 8 rows (4 pairs) per iteration: 4 independent float4 loads/lane.
        #pragma unroll 4
        for (; k + 8 <= nb; k += 8) {
            int rA0 = __shfl_sync(0xffffffffu, myrow, k + 0 + half);
            int rA1 = __shfl_sync(0xffffffffu, myrow, k + 2 + half);
            int rA2 = __shfl_sync(0xffffffffu, myrow, k + 4 + half);
            int rA3 = __shfl_sync(0xffffffffu, myrow, k + 6 + half);
            float4 v0 = __ldcs(&data4[(long long)rA0 * 16 + c]);
            float4 v1 = __ldcs(&data4[(long long)rA1 * 16 + c]);
            float4 v2 = __ldcs(&data4[(long long)rA2 * 16 + c]);
            float4 v3 = __ldcs(&data4[(long long)rA3 * 16 + c]);
            ax += (v0.x + v1.x) + (v2.x + v3.x);
            ay += (v0.y + v1.y) + (v2.y + v3.y);
            az += (v0.z + v1.z) + (v2.z + v3.z);
            aw += (v0.w + v1.w) + (v2.w + v3.w);
        }
        // Pair tail (2 rows at a time)
        for (; k + 2 <= nb; k += 2) {
            int r = __shfl_sync(0xffffffffu, myrow, k + half);
            float4 v = __ldcs(&data4[(long long)r * 16 + c]);
            ax += v.x; ay += v.y; az += v.z; aw += v.w;
        }
        // Odd row: half 0 only
        if (k < nb) {
            int r = __shfl_sync(0xffffffffu, myrow, k);
            if (half == 0) {
                float4 v = __ldcs(&data4[(long long)r * 16 + c]);
                ax += v.x; ay += v.y; az += v.z; aw += v.w;
            }
        }
    }

    // Combine the two halves (lane i += lane i^16).
    ax += __shfl_xor_sync(0xffffffffu, ax, 16);
    ay += __shfl_xor_sync(0xffffffffu, ay, 16);
    az += __shfl_xor_sync(0xffffffffu, az, 16);
    aw += __shfl_xor_sync(0xffffffffu, aw, 16);

    if (half == 0) {
        float inv = (cnt > 0) ? (1.0f / (float)cnt) : 0.0f;
        float4 o;
        o.x = ax * inv; o.y = ay * inv; o.z = az * inv; o.w = aw * inv;
        out4[(long long)warp * 16 + c] = o;
    }
}

extern "C" void kernel_launch(void* const* d_in, const int* in_sizes, int n_in,
                              void* d_out, int out_size) {
    // Identify inputs by element count: data = largest (N*D), ids = N elems.
    int data_idx = 0;
    long long best = -1;
    for (int i = 0; i < n_in; i++) {
        if ((long long)in_sizes[i] > best) { best = in_sizes[i]; data_idx = i; }
    }
    long long n_rows_ll = best / D_DIM;

    int ids_idx = -1;
    for (int i = 0; i < n_in; i++) {
        if (i != data_idx && (long long)in_sizes[i] == n_rows_ll) { ids_idx = i; break; }
    }
    if (ids_idx < 0) {
        for (int i = 0; i < n_in; i++) {
            if (i != data_idx && in_sizes[i] > 1) { ids_idx = i; break; }
        }
    }

    const float* data = (const float*)d_in[data_idx];
    const void*  ids  = d_in[ids_idx];

    int n_rows = (int)n_rows_ll;
    int S = out_size / D_DIM;   // 100,000 segments
    if (S > SEG_CAP) S = SEG_CAP;

    const int TPB = 256;

    // 1. scatter row indices into buckets (4 rows per thread)
    int n_quads = (n_rows + 3) / 4;
    scatter_kernel<<<(n_quads + TPB - 1) / TPB, TPB>>>(ids, n_rows, S);

    // 2. gather-reduce (1 warp per segment; also resets cursors)
    long long g_threads = (long long)S * 32;
    gather_kernel<<<(int)((g_threads + TPB - 1) / TPB), TPB>>>(
        (const float4*)data, (float4*)d_out, S);
}